// round 14
// baseline (speedup 1.0000x reference)
#include <cuda_runtime.h>
#include <cuda_fp16.h>
#include <cstdint>
#include <math.h>

// ---------------------------------------------------------------------------
// Problem constants
// ---------------------------------------------------------------------------
static constexpr int BB      = 4;
static constexpr int NPTS    = 262144;           // points per batch (2^18)
static constexpr int NPLANES = 12;               // B * 3
static constexpr int CH      = 40;
static constexpr int HWIM    = 65536;            // 256*256
static constexpr int TOT     = BB * NPTS;        // 1,048,576
static constexpr int NTILES  = TOT / 128;        // 8192
static constexpr int NTHREADS = 384;             // 8 MMA warps + 4 gather warps

// ---------------------------------------------------------------------------
// Device scratch (static __device__ arrays: allocation-free)
// ---------------------------------------------------------------------------
__device__ __align__(16) __half g_tp[(size_t)NPLANES * HWIM * CH];  // ~63 MB transposed fp16 triplane
__device__ __align__(16) __half g_w[4 * 128 * 128];                 // 4 swizzled W^T tiles (f16)

// ---------------------------------------------------------------------------
// Swizzled tiles. Main tiles: 128 rows x 256B. H-exchange: 128 rows x 128B.
// ---------------------------------------------------------------------------
__host__ __device__ __forceinline__ uint32_t swz(int r, int kb) {
    return (uint32_t)(r * 256 + (kb ^ ((r & 7) << 4)));
}
__device__ __forceinline__ uint32_t swzH(int r, int kb) {
    return (uint32_t)(r * 128 + (kb ^ ((r & 7) << 4)));
}

__device__ __forceinline__ uint32_t smem_u32(const void* p) {
    uint32_t a;
    asm("{ .reg .u64 t; cvta.to.shared.u64 t, %1; cvt.u32.u64 %0, t; }" : "=r"(a) : "l"(p));
    return a;
}

__device__ __forceinline__ uint32_t h2u(__half2 h) {
    uint32_t u;
    *reinterpret_cast<__half2*>(&u) = h;
    return u;
}

__device__ __forceinline__ void ldsm4(uint32_t r[4], uint32_t addr) {
    asm volatile("ldmatrix.sync.aligned.m8n8.x4.shared.b16 {%0,%1,%2,%3}, [%4];"
                 : "=r"(r[0]), "=r"(r[1]), "=r"(r[2]), "=r"(r[3]) : "r"(addr));
}

__device__ __forceinline__ void mma16816(float d[4], const uint32_t a[4], const uint32_t b[2]) {
    asm volatile(
        "mma.sync.aligned.m16n8k16.row.col.f32.f16.f16.f32 "
        "{%0,%1,%2,%3}, {%4,%5,%6,%7}, {%8,%9}, {%0,%1,%2,%3};"
        : "+f"(d[0]), "+f"(d[1]), "+f"(d[2]), "+f"(d[3])
        : "r"(a[0]), "r"(a[1]), "r"(a[2]), "r"(a[3]), "r"(b[0]), "r"(b[1]));
}

// Named barriers: FULL0=1, FULL1=2, EMPTY0=3, EMPTY1=4 (count 384).
// Pair barriers: ids 5..8, count 64 (the two warps of an MMA pair).
#define BAR_SYNC(id)   asm volatile("bar.sync %0, %1;"   :: "r"(id), "r"(NTHREADS) : "memory")
#define BAR_ARRIVE(id) asm volatile("bar.arrive %0, %1;" :: "r"(id), "r"(NTHREADS) : "memory")
#define PAIR_BAR(id)   asm volatile("bar.sync %0, %1;"   :: "r"(id), "r"(64) : "memory")

// ---------------------------------------------------------------------------
// Prep 1: transpose triplane (B,3,C,H,W) f32 -> (plane,H,W,C) f16
// ---------------------------------------------------------------------------
__global__ void k_transpose(const float* __restrict__ tp) {
    int idx = blockIdx.x * blockDim.x + threadIdx.x;
    if (idx >= NPLANES * HWIM) return;
    int plane = idx >> 16;
    int pix   = idx & 65535;
    const float* src = tp + (size_t)plane * CH * HWIM + pix;
    __half tmp[CH];
#pragma unroll
    for (int c = 0; c < CH; c++) tmp[c] = __float2half_rn(__ldg(src + (size_t)c * HWIM));
    uint4* dst = (uint4*)(g_tp + (size_t)idx * CH);
    const uint4* s = (const uint4*)tmp;
#pragma unroll
    for (int i = 0; i < 5; i++) dst[i] = s[i];
}

// ---------------------------------------------------------------------------
// Prep 2: W^T f16 tiles (row n = output, col k = input), zero-padded K.
// ---------------------------------------------------------------------------
__global__ void k_prep_w(const float* __restrict__ dw1, const float* __restrict__ dw2,
                         const float* __restrict__ cw1, const float* __restrict__ cw2) {
    int idx = blockIdx.x * blockDim.x + threadIdx.x;
    if (idx >= 4 * 128 * 128) return;
    int m   = idx >> 14;
    int rem = idx & 16383;
    int n   = rem >> 7;
    int k   = rem & 127;
    const float* W; int K;
    if      (m == 0) { W = dw1; K = 120; }
    else if (m == 1) { W = dw2; K = 128; }
    else if (m == 2) { W = cw1; K = 123; }
    else             { W = cw2; K = 128; }
    float v = (k < K) ? W[k * 128 + n] : 0.0f;
    *(__half*)((char*)g_w + (size_t)m * 32768 + swz(n, 2 * k)) = __float2half_rn(v);
}

// ---------------------------------------------------------------------------
// SMEM map (bytes)
// ---------------------------------------------------------------------------
static constexpr int OFF_BIAS  = 0;            // 1028 floats = 4112 B
static constexpr int OFF_SCR   = 4608;         // gather scratch: 12288 B
static constexpr int OFF_H     = 16896;        // 16 KB h-exchange region (128 rows x 128 B)
static constexpr int OFF_A0    = 33280;        // 32 KB A tile, buffer 0
static constexpr int OFF_A1    = 66048;        // 32 KB A tile, buffer 1
static constexpr int OFF_W     = 98816;        // 4 x 32 KB weight tiles
static constexpr int SMEM_BYTES = OFF_W + 4 * 32768;   // 229888 (<= 232448)

// ---------------------------------------------------------------------------
// Main fused kernel
// ---------------------------------------------------------------------------
__global__ void __launch_bounds__(NTHREADS, 1)
k_main(const float* __restrict__ coords, const float* __restrict__ vdirs,
       const float* __restrict__ db1, const float* __restrict__ db2,
       const float* __restrict__ dw3, const float* __restrict__ db3,
       const float* __restrict__ cb1, const float* __restrict__ cb2,
       const float* __restrict__ cw3, const float* __restrict__ cb3,
       float* __restrict__ out) {
    extern __shared__ __align__(256) char smem[];
    const int tid  = threadIdx.x;
    const int lane = tid & 31;
    float* sb = (float*)(smem + OFF_BIAS);

    // biases / small vectors
    if (tid < 128) {
        sb[tid]       = db1[tid];
        sb[128 + tid] = db2[tid];
        sb[256 + tid] = dw3[tid];
        sb[384 + tid] = cb1[tid];
        sb[512 + tid] = cb2[tid];
        sb[640 + 3 * tid + 0] = cw3[3 * tid + 0];
        sb[640 + 3 * tid + 1] = cw3[3 * tid + 1];
        sb[640 + 3 * tid + 2] = cw3[3 * tid + 2];
    }
    if (tid == 0) {
        sb[1024] = db3[0];
        sb[1025] = cb3[0]; sb[1026] = cb3[1]; sb[1027] = cb3[2];
    }
    // prepped W tiles -> SMEM (128 KB)
    {
        const uint4* src = (const uint4*)g_w;
        uint4* dst = (uint4*)(smem + OFF_W);
        for (int i = tid; i < (4 * 32768) / 16; i += NTHREADS) dst[i] = src[i];
    }
    __syncthreads();

    const uint32_t Au[2] = { smem_u32(smem + OFF_A0), smem_u32(smem + OFF_A1) };
    const uint32_t W0 = smem_u32(smem + OFF_W);            // dw1^T
    const uint32_t W1 = smem_u32(smem + OFF_W + 32768);    // dw2^T
    const uint32_t W2 = smem_u32(smem + OFF_W + 65536);    // cw1^T
    const uint32_t W3 = smem_u32(smem + OFF_W + 98304);    // cw2^T
    const uint32_t Hr = smem_u32(smem + OFF_H);
    char* Hc = smem + OFF_H;

    if (tid >= 256) {
        // ========== GATHER WARPS (4 warps, corner-cooperative) ==========
        const int gpt = tid - 256;         // point slot 0..127
        const int g   = gpt >> 5;          // gather warp id 0..3
        const int grp = lane / 5;          // 5-lane job group 0..5 (6 inactive)
        const int li  = lane % 5;          // uint4 index within 80B texel
        uint2* scr = (uint2*)(smem + OFF_SCR);
        const char* tpb = (const char*)g_tp;
        int lt = 0;
        for (int tile = blockIdx.x; tile < NTILES; tile += gridDim.x, lt++) {
            int b = lt & 1;
            if (lt >= 2) BAR_SYNC(3 + b);          // wait A[b] empty
            char* As = smem + (b ? OFF_A1 : OFF_A0);
            int pt = tile * 128 + gpt;

            // --- stage 1: per-lane address/weight computation -> scratch ---
            float x = coords[3 * pt], y = coords[3 * pt + 1], z = coords[3 * pt + 2];
            int bb = pt >> 18;  // NPTS = 2^18
            float us[3] = {x, x, y};
            float vs[3] = {y, z, z};
#pragma unroll
            for (int p = 0; p < 3; p++) {
                float ix = fmaf(us[p], 128.0f, 127.5f);
                float iy = fmaf(vs[p], 128.0f, 127.5f);
                float fx0 = floorf(ix), fy0 = floorf(iy);
                float fx = ix - fx0, fy = iy - fy0;
                int x0 = (int)fx0, y0 = (int)fy0;
                float w00 = (1.0f - fx) * (1.0f - fy);
                float w10 = fx * (1.0f - fy);
                float w01 = (1.0f - fx) * fy;
                float w11 = fx * fy;
                if (x0 < 0)   { w00 = 0.0f; w01 = 0.0f; }
                if (x0 > 254) { w10 = 0.0f; w11 = 0.0f; }
                if (y0 < 0)   { w00 = 0.0f; w10 = 0.0f; }
                if (y0 > 254) { w01 = 0.0f; w11 = 0.0f; }
                int xc0 = max(x0, 0), yc0 = max(y0, 0);
                int xc1 = min(x0 + 1, 255), yc1 = min(y0 + 1, 255);
                uint32_t pb = (uint32_t)(bb * 3 + p) * (uint32_t)(HWIM * CH * 2);
                uint2* sj = scr + (((g * 96 + lane * 3 + p)) << 2);
                sj[0] = make_uint2(pb + (uint32_t)(yc0 * 256 + xc0) * 80u, __float_as_uint(w00));
                sj[1] = make_uint2(pb + (uint32_t)(yc0 * 256 + xc1) * 80u, __float_as_uint(w10));
                sj[2] = make_uint2(pb + (uint32_t)(yc1 * 256 + xc0) * 80u, __float_as_uint(w01));
                sj[3] = make_uint2(pb + (uint32_t)(yc1 * 256 + xc1) * 80u, __float_as_uint(w11));
            }
            __syncwarp();

            // --- stage 2: 5-lane groups, one (pt,plane) job each ---
            if (grp < 6) {
#pragma unroll 2
                for (int it = 0; it < 16; it++) {
                    int j = it * 6 + grp;                  // 0..95
                    const uint2* sj = scr + ((g * 96 + j) << 2);
                    float2 a0 = {0.f, 0.f}, a1 = {0.f, 0.f}, a2 = {0.f, 0.f}, a3 = {0.f, 0.f};
#pragma unroll
                    for (int c = 0; c < 4; c++) {
                        uint2 aw = sj[c];
                        float w = __uint_as_float(aw.y);
                        uint4 qv = *(const uint4*)(tpb + aw.x + (uint32_t)(li * 16));
                        const __half2* hq = (const __half2*)&qv;
                        float2 f0 = __half22float2(hq[0]);
                        float2 f1 = __half22float2(hq[1]);
                        float2 f2 = __half22float2(hq[2]);
                        float2 f3 = __half22float2(hq[3]);
                        a0.x = fmaf(f0.x, w, a0.x); a0.y = fmaf(f0.y, w, a0.y);
                        a1.x = fmaf(f1.x, w, a1.x); a1.y = fmaf(f1.y, w, a1.y);
                        a2.x = fmaf(f2.x, w, a2.x); a2.y = fmaf(f2.y, w, a2.y);
                        a3.x = fmaf(f3.x, w, a3.x); a3.y = fmaf(f3.y, w, a3.y);
                    }
                    int lp = j / 3, p = j - 3 * lp;
                    int r = g * 32 + lp;
                    uint4 o;
                    o.x = h2u(__float22half2_rn(a0));
                    o.y = h2u(__float22half2_rn(a1));
                    o.z = h2u(__float22half2_rn(a2));
                    o.w = h2u(__float22half2_rn(a3));
                    *(uint4*)(As + swz(r, p * 80 + li * 16)) = o;
                }
            }

            // --- view dirs + zero pad (cols 120..127) ---
            {
                float vx = vdirs[3 * pt], vy = vdirs[3 * pt + 1], vz = vdirs[3 * pt + 2];
                uint4 o;
                o.x = h2u(__floats2half2_rn(vx, vy));
                o.y = h2u(__floats2half2_rn(vz, 0.0f));
                o.z = 0u; o.w = 0u;
                *(uint4*)(As + swz(gpt, 240)) = o;
            }
            __syncwarp();
            BAR_ARRIVE(1 + b);                     // signal A[b] full
        }
    } else {
        // ============ MMA WARPS (wid 0-7): M=32 x N=64 per warp ============
        // Pair p = wid>>1 owns rows [32p, 32p+32); half hh = wid&1 owns
        // output cols [64*hh, 64*hh+64).
        const int wid  = tid >> 5;
        const int hh   = wid & 1;
        const int p    = wid >> 1;
        const int m0   = p * 32;
        const int nb   = hh * 64;
        const int pbar = 5 + p;
        const int arow = lane & 15, acolh = (lane >> 4) * 8;
        const int brow = ((lane >> 4) << 3) + (lane & 7), bcol = ((lane >> 3) & 1) * 8;
        const int q = lane >> 2, coff = (lane & 3) * 2;
        float acc[2][8][4];
        uint32_t ah[2][4][4];
        int lt = 0;
        for (int tile = blockIdx.x; tile < NTILES; tile += gridDim.x, lt++) {
            int b = lt & 1;
            BAR_SYNC(1 + b);                       // wait A[b] full
            uint32_t A = Au[b];

#pragma unroll
            for (int pass = 0; pass < 2; pass++) {
                // pass 0 = density (W0,W1,db1,db2,dw3,db3)
                // pass 1 = color   (W2,W3,cb1,cb2,cw3,cb3)
                const uint32_t Wa = pass ? W2 : W0;
                const uint32_t Wb = pass ? W3 : W1;
                const float* b1v = pass ? sb + 384 : sb;
                const float* b2v = pass ? sb + 512 : sb + 128;

                // ---- layer 1: acc = A(rows m0..m0+31) x Wa^T(cols nb..nb+63) ----
#pragma unroll
                for (int mt = 0; mt < 2; mt++)
#pragma unroll
                    for (int nt = 0; nt < 8; nt++)
#pragma unroll
                        for (int i = 0; i < 4; i++) acc[mt][nt][i] = 0.0f;
#pragma unroll
                for (int k0 = 0; k0 < 128; k0 += 16) {
                    uint32_t a0[4], a1[4];
                    ldsm4(a0, A + swz(m0 + arow,      2 * (k0 + acolh)));
                    ldsm4(a1, A + swz(m0 + 16 + arow, 2 * (k0 + acolh)));
#pragma unroll
                    for (int jn = 0; jn < 4; jn++) {
                        uint32_t bf[4];
                        ldsm4(bf, Wa + swz(nb + jn * 16 + brow, 2 * (k0 + bcol)));
                        mma16816(acc[0][2 * jn],     a0, bf);
                        mma16816(acc[0][2 * jn + 1], a0, bf + 2);
                        mma16816(acc[1][2 * jn],     a1, bf);
                        mma16816(acc[1][2 * jn + 1], a1, bf + 2);
                    }
                }
                if (pass == 1) BAR_ARRIVE(3 + b);  // A[b] fully consumed

                // ---- convert: bias + ReLU + fp16, own-half A-frags ----
#pragma unroll
                for (int mt = 0; mt < 2; mt++)
#pragma unroll
                    for (int kk = 0; kk < 4; kk++) {
                        int c0 = nb + 16 * kk + coff;
                        int c1 = c0 + 8;
                        float b00 = b1v[c0], b01 = b1v[c0 + 1];
                        float b10 = b1v[c1], b11 = b1v[c1 + 1];
                        const float* d0 = acc[mt][2 * kk];
                        const float* d1 = acc[mt][2 * kk + 1];
                        float2 v;
                        v.x = fmaxf(d0[0] + b00, 0.f); v.y = fmaxf(d0[1] + b01, 0.f);
                        ah[mt][kk][0] = h2u(__float22half2_rn(v));
                        v.x = fmaxf(d0[2] + b00, 0.f); v.y = fmaxf(d0[3] + b01, 0.f);
                        ah[mt][kk][1] = h2u(__float22half2_rn(v));
                        v.x = fmaxf(d1[0] + b10, 0.f); v.y = fmaxf(d1[1] + b11, 0.f);
                        ah[mt][kk][2] = h2u(__float22half2_rn(v));
                        v.x = fmaxf(d1[2] + b10, 0.f); v.y = fmaxf(d1[3] + b11, 0.f);
                        ah[mt][kk][3] = h2u(__float22half2_rn(v));
                    }

                // ---- layer 2: own k-groups from regs ----
#pragma unroll
                for (int mt = 0; mt < 2; mt++)
#pragma unroll
                    for (int nt = 0; nt < 8; nt++)
#pragma unroll
                        for (int i = 0; i < 4; i++) acc[mt][nt][i] = 0.0f;
#pragma unroll
                for (int kk = 0; kk < 4; kk++) {
                    int kgg = 4 * hh + kk;
#pragma unroll
                    for (int jn = 0; jn < 4; jn++) {
                        uint32_t bf[4];
                        ldsm4(bf, Wb + swz(nb + jn * 16 + brow, 2 * (16 * kgg + bcol)));
                        mma16816(acc[0][2 * jn],     ah[0][kk], bf);
                        mma16816(acc[0][2 * jn + 1], ah[0][kk], bf + 2);
                        mma16816(acc[1][2 * jn],     ah[1][kk], bf);
                        mma16816(acc[1][2 * jn + 1], ah[1][kk], bf + 2);
                    }
                }
                // ---- layer 2: partner k-groups via 2-round SMEM exchange ----
#pragma unroll
                for (int r = 0; r < 2; r++) {
                    // store own kg {2r, 2r+1}
#pragma unroll
                    for (int t = 0; t < 2; t++) {
                        int kk = 2 * r + t;
                        int rc = 32 * hh + 16 * t;
#pragma unroll
                        for (int mt = 0; mt < 2; mt++) {
                            int row = m0 + 16 * mt + q;
                            *(uint32_t*)(Hc + swzH(row,     2 * (rc + coff)))     = ah[mt][kk][0];
                            *(uint32_t*)(Hc + swzH(row + 8, 2 * (rc + coff)))     = ah[mt][kk][1];
                            *(uint32_t*)(Hc + swzH(row,     2 * (rc + 8 + coff))) = ah[mt][kk][2];
                            *(uint32_t*)(Hc + swzH(row + 8, 2 * (rc + 8 + coff))) = ah[mt][kk][3];
                        }
                    }
                    PAIR_BAR(pbar);
                    // read partner kg {4(1-hh)+2r, +1} and accumulate
#pragma unroll
                    for (int t = 0; t < 2; t++) {
                        int kgg = 4 * (1 - hh) + 2 * r + t;
                        int rc  = 32 * (1 - hh) + 16 * t;
                        uint32_t a0[4], a1[4];
                        ldsm4(a0, Hr + swzH(m0 + arow,      2 * (rc + acolh)));
                        ldsm4(a1, Hr + swzH(m0 + 16 + arow, 2 * (rc + acolh)));
#pragma unroll
                        for (int jn = 0; jn < 4; jn++) {
                            uint32_t bf[4];
                            ldsm4(bf, Wb + swz(nb + jn * 16 + brow, 2 * (16 * kgg + bcol)));
                            mma16816(acc[0][2 * jn],     a0, bf);
                            mma16816(acc[0][2 * jn + 1], a0, bf + 2);
                            mma16816(acc[1][2 * jn],     a1, bf);
                            mma16816(acc[1][2 * jn + 1], a1, bf + 2);
                        }
                    }
                    PAIR_BAR(pbar);
                }

                // ---- head: per-row dot over own 64 cols, pair-combine ----
                if (pass == 0) {
                    float pr[2][2] = {{0.f, 0.f}, {0.f, 0.f}};
#pragma unroll
                    for (int mt = 0; mt < 2; mt++)
#pragma unroll
                        for (int nt = 0; nt < 8; nt++) {
                            int c = nb + nt * 8 + coff;
                            float b0 = sb[128 + c], b1 = sb[128 + c + 1];
                            float w0 = sb[256 + c], w1 = sb[256 + c + 1];
                            pr[mt][0] = fmaf(fmaxf(acc[mt][nt][0] + b0, 0.f), w0, pr[mt][0]);
                            pr[mt][0] = fmaf(fmaxf(acc[mt][nt][1] + b1, 0.f), w1, pr[mt][0]);
                            pr[mt][1] = fmaf(fmaxf(acc[mt][nt][2] + b0, 0.f), w0, pr[mt][1]);
                            pr[mt][1] = fmaf(fmaxf(acc[mt][nt][3] + b1, 0.f), w1, pr[mt][1]);
                        }
#pragma unroll
                    for (int mt = 0; mt < 2; mt++)
#pragma unroll
                        for (int h = 0; h < 2; h++) {
                            float v = pr[mt][h];
                            v += __shfl_xor_sync(0xFFFFFFFFu, v, 1);
                            v += __shfl_xor_sync(0xFFFFFFFFu, v, 2);
                            if ((lane & 3) == 0) {
                                int rl = 16 * mt + q + 8 * h;
                                *(float*)(Hc + (m0 + rl) * 128 + hh * 64) = v;
                            }
                        }
                    PAIR_BAR(pbar);
                    if (hh == 0 && (lane & 3) == 0) {
#pragma unroll
                        for (int mt = 0; mt < 2; mt++)
#pragma unroll
                            for (int h = 0; h < 2; h++) {
                                int rl = 16 * mt + q + 8 * h;
                                float v = *(float*)(Hc + (m0 + rl) * 128)
                                        + *(float*)(Hc + (m0 + rl) * 128 + 64) + sb[1024];
                                out[tile * 128 + m0 + rl] = v;
                            }
                    }
                    PAIR_BAR(pbar);
                } else {
                    float pr[2][2][3];
#pragma unroll
                    for (int mt = 0; mt < 2; mt++)
#pragma unroll
                        for (int h = 0; h < 2; h++)
#pragma unroll
                            for (int ch = 0; ch < 3; ch++) pr[mt][h][ch] = 0.f;
#pragma unroll
                    for (int mt = 0; mt < 2; mt++)
#pragma unroll
                        for (int nt = 0; nt < 8; nt++) {
                            int c = nb + nt * 8 + coff;
                            float b0 = sb[512 + c], b1 = sb[512 + c + 1];
                            float g0 = fmaxf(acc[mt][nt][0] + b0, 0.f);
                            float g1 = fmaxf(acc[mt][nt][1] + b1, 0.f);
                            float g2 = fmaxf(acc[mt][nt][2] + b0, 0.f);
                            float g3 = fmaxf(acc[mt][nt][3] + b1, 0.f);
#pragma unroll
                            for (int ch = 0; ch < 3; ch++) {
                                float wc0 = sb[640 + 3 * c + ch];
                                float wc1 = sb[640 + 3 * (c + 1) + ch];
                                pr[mt][0][ch] = fmaf(g0, wc0, pr[mt][0][ch]);
                                pr[mt][0][ch] = fmaf(g1, wc1, pr[mt][0][ch]);
                                pr[mt][1][ch] = fmaf(g2, wc0, pr[mt][1][ch]);
                                pr[mt][1][ch] = fmaf(g3, wc1, pr[mt][1][ch]);
                            }
                        }
#pragma unroll
                    for (int mt = 0; mt < 2; mt++)
#pragma unroll
                        for (int h = 0; h < 2; h++) {
                            float v0 = pr[mt][h][0], v1 = pr[mt][h][1], v2 = pr[mt][h][2];
                            v0 += __shfl_xor_sync(0xFFFFFFFFu, v0, 1);
                            v0 += __shfl_xor_sync(0xFFFFFFFFu, v0, 2);
                            v1 += __shfl_xor_sync(0xFFFFFFFFu, v1, 1);
                            v1 += __shfl_xor_sync(0xFFFFFFFFu, v1, 2);
                            v2 += __shfl_xor_sync(0xFFFFFFFFu, v2, 1);
                            v2 += __shfl_xor_sync(0xFFFFFFFFu, v2, 2);
                            if ((lane & 3) == 0) {
                                int rl = 16 * mt + q + 8 * h;
                                float* hs = (float*)(Hc + (m0 + rl) * 128 + hh * 64);
                                hs[0] = v0; hs[1] = v1; hs[2] = v2;
                            }
                        }
                    PAIR_BAR(pbar);
                    if (hh == 0 && (lane & 3) == 0) {
#pragma unroll
                        for (int mt = 0; mt < 2; mt++)
#pragma unroll
                            for (int h = 0; h < 2; h++) {
                                int rl = 16 * mt + q + 8 * h;
                                const float* h0 = (const float*)(Hc + (m0 + rl) * 128);
                                const float* h1 = (const float*)(Hc + (m0 + rl) * 128 + 64);
                                float* ro = out + TOT + 3 * (tile * 128 + m0 + rl);
                                ro[0] = 1.0f / (1.0f + __expf(-(h0[0] + h1[0] + sb[1025])));
                                ro[1] = 1.0f / (1.0f + __expf(-(h0[1] + h1[1] + sb[1026])));
                                ro[2] = 1.0f / (1.0f + __expf(-(h0[2] + h1[2] + sb[1027])));
                            }
                    }
                    PAIR_BAR(pbar);
                }
            }
        }
    }
}

// ---------------------------------------------------------------------------
// kernel_launch
// ---------------------------------------------------------------------------
extern "C" void kernel_launch(void* const* d_in, const int* in_sizes, int n_in,
                              void* d_out, int out_size) {
    const float* triplane = (const float*)d_in[0];
    const float* coords   = (const float*)d_in[1];
    const float* vdirs    = (const float*)d_in[2];
    const float* dw1 = (const float*)d_in[3];
    const float* db1 = (const float*)d_in[4];
    const float* dw2 = (const float*)d_in[5];
    const float* db2 = (const float*)d_in[6];
    const float* dw3 = (const float*)d_in[7];
    const float* db3 = (const float*)d_in[8];
    const float* cw1 = (const float*)d_in[9];
    const float* cb1 = (const float*)d_in[10];
    const float* cw2 = (const float*)d_in[11];
    const float* cb2 = (const float*)d_in[12];
    const float* cw3 = (const float*)d_in[13];
    const float* cb3 = (const float*)d_in[14];
    float* out = (float*)d_out;

    k_transpose<<<(NPLANES * HWIM + 255) / 256, 256>>>(triplane);
    k_prep_w<<<(4 * 128 * 128 + 255) / 256, 256>>>(dw1, dw2, cw1, cw2);

    int dev = 0, sms = 148;
    cudaGetDevice(&dev);
    cudaDeviceGetAttribute(&sms, cudaDevAttrMultiProcessorCount, dev);
    cudaFuncSetAttribute(k_main, cudaFuncAttributeMaxDynamicSharedMemorySize, SMEM_BYTES);
    k_main<<<sms, NTHREADS, SMEM_BYTES>>>(coords, vdirs, db1, db2, dw3, db3,
                                          cb1, cb2, cw3, cb3, out);
}

// round 15
// speedup vs baseline: 1.0324x; 1.0324x over previous
#include <cuda_runtime.h>
#include <cuda_fp16.h>
#include <cstdint>
#include <math.h>

// ---------------------------------------------------------------------------
// Problem constants
// ---------------------------------------------------------------------------
static constexpr int BB      = 4;
static constexpr int NPTS    = 262144;           // points per batch (2^18)
static constexpr int NPLANES = 12;               // B * 3
static constexpr int CH      = 40;
static constexpr int HWIM    = 65536;            // 256*256
static constexpr int TOT     = BB * NPTS;        // 1,048,576
static constexpr int NTILES  = TOT / 128;        // 8192
static constexpr int NTHREADS = 384;             // 8 MMA warps + 4 gather warps

// ---------------------------------------------------------------------------
// Device scratch (static __device__ arrays: allocation-free)
// ---------------------------------------------------------------------------
__device__ __align__(16) __half g_tp[(size_t)NPLANES * HWIM * CH];  // ~63 MB transposed fp16 triplane
__device__ __align__(16) __half g_w[4 * 128 * 128];                 // 4 swizzled W^T tiles (f16)
__device__ int g_dummy;

// ---------------------------------------------------------------------------
// Swizzled tiles. Main tiles: 128 rows x 256B. H-exchange: 128 rows x 128B.
// ---------------------------------------------------------------------------
__host__ __device__ __forceinline__ uint32_t swz(int r, int kb) {
    return (uint32_t)(r * 256 + (kb ^ ((r & 7) << 4)));
}
__device__ __forceinline__ uint32_t swzH(int r, int kb) {
    return (uint32_t)(r * 128 + (kb ^ ((r & 7) << 4)));
}

__device__ __forceinline__ uint32_t smem_u32(const void* p) {
    uint32_t a;
    asm("{ .reg .u64 t; cvta.to.shared.u64 t, %1; cvt.u32.u64 %0, t; }" : "=r"(a) : "l"(p));
    return a;
}

__device__ __forceinline__ uint32_t h2u(__half2 h) {
    uint32_t u;
    *reinterpret_cast<__half2*>(&u) = h;
    return u;
}

__device__ __forceinline__ void ldsm4(uint32_t r[4], uint32_t addr) {
    asm volatile("ldmatrix.sync.aligned.m8n8.x4.shared.b16 {%0,%1,%2,%3}, [%4];"
                 : "=r"(r[0]), "=r"(r[1]), "=r"(r[2]), "=r"(r[3]) : "r"(addr));
}

__device__ __forceinline__ void mma16816(float d[4], const uint32_t a[4], const uint32_t b[2]) {
    asm volatile(
        "mma.sync.aligned.m16n8k16.row.col.f32.f16.f16.f32 "
        "{%0,%1,%2,%3}, {%4,%5,%6,%7}, {%8,%9}, {%0,%1,%2,%3};"
        : "+f"(d[0]), "+f"(d[1]), "+f"(d[2]), "+f"(d[3])
        : "r"(a[0]), "r"(a[1]), "r"(a[2]), "r"(a[3]), "r"(b[0]), "r"(b[1]));
}

// Named barriers: FULL0=1, FULL1=2, EMPTY0=3, EMPTY1=4 (count 384).
// Pair barriers: ids 5..8, count 64 (the two warps of an MMA pair).
#define BAR_SYNC(id)   asm volatile("bar.sync %0, %1;"   :: "r"(id), "r"(NTHREADS) : "memory")
#define BAR_ARRIVE(id) asm volatile("bar.arrive %0, %1;" :: "r"(id), "r"(NTHREADS) : "memory")
#define PAIR_BAR(id)   asm volatile("bar.sync %0, %1;"   :: "r"(id), "r"(64) : "memory")

// ---------------------------------------------------------------------------
// Prep 0: dummy kernel — shifts ncu's -s 5 capture slot onto k_main.
// ---------------------------------------------------------------------------
__global__ void k_dummy() {
    if (threadIdx.x == 0 && blockIdx.x == 0) g_dummy = 1;
}

// ---------------------------------------------------------------------------
// Prep 1: transpose triplane (B,3,C,H,W) f32 -> (plane,H,W,C) f16
// ---------------------------------------------------------------------------
__global__ void k_transpose(const float* __restrict__ tp) {
    int idx = blockIdx.x * blockDim.x + threadIdx.x;
    if (idx >= NPLANES * HWIM) return;
    int plane = idx >> 16;
    int pix   = idx & 65535;
    const float* src = tp + (size_t)plane * CH * HWIM + pix;
    __half tmp[CH];
#pragma unroll
    for (int c = 0; c < CH; c++) tmp[c] = __float2half_rn(__ldg(src + (size_t)c * HWIM));
    uint4* dst = (uint4*)(g_tp + (size_t)idx * CH);
    const uint4* s = (const uint4*)tmp;
#pragma unroll
    for (int i = 0; i < 5; i++) dst[i] = s[i];
}

// ---------------------------------------------------------------------------
// Prep 2: W^T f16 tiles (row n = output, col k = input), zero-padded K.
// ---------------------------------------------------------------------------
__global__ void k_prep_w(const float* __restrict__ dw1, const float* __restrict__ dw2,
                         const float* __restrict__ cw1, const float* __restrict__ cw2) {
    int idx = blockIdx.x * blockDim.x + threadIdx.x;
    if (idx >= 4 * 128 * 128) return;
    int m   = idx >> 14;
    int rem = idx & 16383;
    int n   = rem >> 7;
    int k   = rem & 127;
    const float* W; int K;
    if      (m == 0) { W = dw1; K = 120; }
    else if (m == 1) { W = dw2; K = 128; }
    else if (m == 2) { W = cw1; K = 123; }
    else             { W = cw2; K = 128; }
    float v = (k < K) ? W[k * 128 + n] : 0.0f;
    *(__half*)((char*)g_w + (size_t)m * 32768 + swz(n, 2 * k)) = __float2half_rn(v);
}

// ---------------------------------------------------------------------------
// SMEM map (bytes)
// ---------------------------------------------------------------------------
static constexpr int OFF_BIAS  = 0;            // 1028 floats = 4112 B
static constexpr int OFF_SCR   = 4608;         // gather scratch: 12288 B
static constexpr int OFF_H     = 16896;        // 16 KB h-exchange region (128 rows x 128 B)
static constexpr int OFF_A0    = 33280;        // 32 KB A tile, buffer 0
static constexpr int OFF_A1    = 66048;        // 32 KB A tile, buffer 1
static constexpr int OFF_W     = 98816;        // 4 x 32 KB weight tiles
static constexpr int SMEM_BYTES = OFF_W + 4 * 32768;   // 229888 (<= 232448)

// ---------------------------------------------------------------------------
// Main fused kernel
// ---------------------------------------------------------------------------
__global__ void __launch_bounds__(NTHREADS, 1)
k_main(const float* __restrict__ coords, const float* __restrict__ vdirs,
       const float* __restrict__ db1, const float* __restrict__ db2,
       const float* __restrict__ dw3, const float* __restrict__ db3,
       const float* __restrict__ cb1, const float* __restrict__ cb2,
       const float* __restrict__ cw3, const float* __restrict__ cb3,
       float* __restrict__ out) {
    extern __shared__ __align__(256) char smem[];
    const int tid  = threadIdx.x;
    const int lane = tid & 31;
    float* sb = (float*)(smem + OFF_BIAS);

    // biases / small vectors
    if (tid < 128) {
        sb[tid]       = db1[tid];
        sb[128 + tid] = db2[tid];
        sb[256 + tid] = dw3[tid];
        sb[384 + tid] = cb1[tid];
        sb[512 + tid] = cb2[tid];
        sb[640 + 3 * tid + 0] = cw3[3 * tid + 0];
        sb[640 + 3 * tid + 1] = cw3[3 * tid + 1];
        sb[640 + 3 * tid + 2] = cw3[3 * tid + 2];
    }
    if (tid == 0) {
        sb[1024] = db3[0];
        sb[1025] = cb3[0]; sb[1026] = cb3[1]; sb[1027] = cb3[2];
    }
    // prepped W tiles -> SMEM (128 KB)
    {
        const uint4* src = (const uint4*)g_w;
        uint4* dst = (uint4*)(smem + OFF_W);
        for (int i = tid; i < (4 * 32768) / 16; i += NTHREADS) dst[i] = src[i];
    }
    __syncthreads();

    const uint32_t Au[2] = { smem_u32(smem + OFF_A0), smem_u32(smem + OFF_A1) };
    const uint32_t W0 = smem_u32(smem + OFF_W);            // dw1^T
    const uint32_t W1 = smem_u32(smem + OFF_W + 32768);    // dw2^T
    const uint32_t W2 = smem_u32(smem + OFF_W + 65536);    // cw1^T
    const uint32_t W3 = smem_u32(smem + OFF_W + 98304);    // cw2^T
    const uint32_t Hr = smem_u32(smem + OFF_H);
    char* Hc = smem + OFF_H;

    if (tid >= 256) {
        // ========== GATHER WARPS (4 warps, corner-cooperative) ==========
        const int gpt = tid - 256;         // point slot 0..127
        const int g   = gpt >> 5;          // gather warp id 0..3
        const int grp = lane / 5;          // 5-lane job group 0..5 (6 inactive)
        const int li  = lane % 5;          // uint4 index within 80B texel
        uint2* scr = (uint2*)(smem + OFF_SCR);
        const char* tpb = (const char*)g_tp;
        int lt = 0;
        for (int tile = blockIdx.x; tile < NTILES; tile += gridDim.x, lt++) {
            int b = lt & 1;
            if (lt >= 2) BAR_SYNC(3 + b);          // wait A[b] empty
            char* As = smem + (b ? OFF_A1 : OFF_A0);
            int pt = tile * 128 + gpt;

            // --- stage 1: per-lane address/weight computation -> scratch ---
            float x = coords[3 * pt], y = coords[3 * pt + 1], z = coords[3 * pt + 2];
            int bb = pt >> 18;  // NPTS = 2^18
            float us[3] = {x, x, y};
            float vs[3] = {y, z, z};
#pragma unroll
            for (int p = 0; p < 3; p++) {
                float ix = fmaf(us[p], 128.0f, 127.5f);
                float iy = fmaf(vs[p], 128.0f, 127.5f);
                float fx0 = floorf(ix), fy0 = floorf(iy);
                float fx = ix - fx0, fy = iy - fy0;
                int x0 = (int)fx0, y0 = (int)fy0;
                float w00 = (1.0f - fx) * (1.0f - fy);
                float w10 = fx * (1.0f - fy);
                float w01 = (1.0f - fx) * fy;
                float w11 = fx * fy;
                if (x0 < 0)   { w00 = 0.0f; w01 = 0.0f; }
                if (x0 > 254) { w10 = 0.0f; w11 = 0.0f; }
                if (y0 < 0)   { w00 = 0.0f; w10 = 0.0f; }
                if (y0 > 254) { w01 = 0.0f; w11 = 0.0f; }
                int xc0 = max(x0, 0), yc0 = max(y0, 0);
                int xc1 = min(x0 + 1, 255), yc1 = min(y0 + 1, 255);
                uint32_t pb = (uint32_t)(bb * 3 + p) * (uint32_t)(HWIM * CH * 2);
                uint2* sj = scr + (((g * 96 + lane * 3 + p)) << 2);
                sj[0] = make_uint2(pb + (uint32_t)(yc0 * 256 + xc0) * 80u, __float_as_uint(w00));
                sj[1] = make_uint2(pb + (uint32_t)(yc0 * 256 + xc1) * 80u, __float_as_uint(w10));
                sj[2] = make_uint2(pb + (uint32_t)(yc1 * 256 + xc0) * 80u, __float_as_uint(w01));
                sj[3] = make_uint2(pb + (uint32_t)(yc1 * 256 + xc1) * 80u, __float_as_uint(w11));
            }
            __syncwarp();

            // --- stage 2: 5-lane groups, software-pipelined (depth 2) ---
            if (grp < 6) {
                uint2 cw[4];
                uint4 qd[4];
                {
                    const uint2* sj = scr + ((g * 96 + grp) << 2);
#pragma unroll
                    for (int c = 0; c < 4; c++) cw[c] = sj[c];
#pragma unroll
                    for (int c = 0; c < 4; c++)
                        qd[c] = *(const uint4*)(tpb + cw[c].x + (uint32_t)(li * 16));
                }
#pragma unroll
                for (int it = 0; it < 16; it++) {
                    uint2 cw2[4];
                    uint4 qd2[4];
                    if (it < 15) {                 // preload iteration it+1
                        const uint2* sj = scr + ((g * 96 + (it + 1) * 6 + grp) << 2);
#pragma unroll
                        for (int c = 0; c < 4; c++) cw2[c] = sj[c];
#pragma unroll
                        for (int c = 0; c < 4; c++)
                            qd2[c] = *(const uint4*)(tpb + cw2[c].x + (uint32_t)(li * 16));
                    }
                    // compute with current iteration's data
                    float2 a0 = {0.f, 0.f}, a1 = {0.f, 0.f}, a2 = {0.f, 0.f}, a3 = {0.f, 0.f};
#pragma unroll
                    for (int c = 0; c < 4; c++) {
                        float w = __uint_as_float(cw[c].y);
                        const __half2* hq = (const __half2*)&qd[c];
                        float2 f0 = __half22float2(hq[0]);
                        float2 f1 = __half22float2(hq[1]);
                        float2 f2 = __half22float2(hq[2]);
                        float2 f3 = __half22float2(hq[3]);
                        a0.x = fmaf(f0.x, w, a0.x); a0.y = fmaf(f0.y, w, a0.y);
                        a1.x = fmaf(f1.x, w, a1.x); a1.y = fmaf(f1.y, w, a1.y);
                        a2.x = fmaf(f2.x, w, a2.x); a2.y = fmaf(f2.y, w, a2.y);
                        a3.x = fmaf(f3.x, w, a3.x); a3.y = fmaf(f3.y, w, a3.y);
                    }
                    int j = it * 6 + grp;
                    int lp = j / 3, p = j - 3 * lp;
                    int r = g * 32 + lp;
                    uint4 o;
                    o.x = h2u(__float22half2_rn(a0));
                    o.y = h2u(__float22half2_rn(a1));
                    o.z = h2u(__float22half2_rn(a2));
                    o.w = h2u(__float22half2_rn(a3));
                    *(uint4*)(As + swz(r, p * 80 + li * 16)) = o;
                    if (it < 15) {
#pragma unroll
                        for (int c = 0; c < 4; c++) { cw[c] = cw2[c]; qd[c] = qd2[c]; }
                    }
                }
            }

            // --- view dirs + zero pad (cols 120..127) ---
            {
                float vx = vdirs[3 * pt], vy = vdirs[3 * pt + 1], vz = vdirs[3 * pt + 2];
                uint4 o;
                o.x = h2u(__floats2half2_rn(vx, vy));
                o.y = h2u(__floats2half2_rn(vz, 0.0f));
                o.z = 0u; o.w = 0u;
                *(uint4*)(As + swz(gpt, 240)) = o;
            }
            __syncwarp();
            BAR_ARRIVE(1 + b);                     // signal A[b] full
        }
    } else {
        // ============ MMA WARPS (wid 0-7): M=32 x N=64 per warp ============
        const int wid  = tid >> 5;
        const int hh   = wid & 1;
        const int p    = wid >> 1;
        const int m0   = p * 32;
        const int nb   = hh * 64;
        const int pbar = 5 + p;
        const int arow = lane & 15, acolh = (lane >> 4) * 8;
        const int brow = ((lane >> 4) << 3) + (lane & 7), bcol = ((lane >> 3) & 1) * 8;
        const int q = lane >> 2, coff = (lane & 3) * 2;
        float acc[2][8][4];
        uint32_t ah[2][4][4];
        int lt = 0;
        for (int tile = blockIdx.x; tile < NTILES; tile += gridDim.x, lt++) {
            int b = lt & 1;
            BAR_SYNC(1 + b);                       // wait A[b] full
            uint32_t A = Au[b];

#pragma unroll
            for (int pass = 0; pass < 2; pass++) {
                const uint32_t Wa = pass ? W2 : W0;
                const uint32_t Wb = pass ? W3 : W1;
                const float* b1v = pass ? sb + 384 : sb;

                // ---- layer 1 ----
#pragma unroll
                for (int mt = 0; mt < 2; mt++)
#pragma unroll
                    for (int nt = 0; nt < 8; nt++)
#pragma unroll
                        for (int i = 0; i < 4; i++) acc[mt][nt][i] = 0.0f;
#pragma unroll
                for (int k0 = 0; k0 < 128; k0 += 16) {
                    uint32_t a0[4], a1[4];
                    ldsm4(a0, A + swz(m0 + arow,      2 * (k0 + acolh)));
                    ldsm4(a1, A + swz(m0 + 16 + arow, 2 * (k0 + acolh)));
#pragma unroll
                    for (int jn = 0; jn < 4; jn++) {
                        uint32_t bf[4];
                        ldsm4(bf, Wa + swz(nb + jn * 16 + brow, 2 * (k0 + bcol)));
                        mma16816(acc[0][2 * jn],     a0, bf);
                        mma16816(acc[0][2 * jn + 1], a0, bf + 2);
                        mma16816(acc[1][2 * jn],     a1, bf);
                        mma16816(acc[1][2 * jn + 1], a1, bf + 2);
                    }
                }
                if (pass == 1) BAR_ARRIVE(3 + b);  // A[b] fully consumed

                // ---- convert: bias + ReLU + fp16, own-half A-frags ----
#pragma unroll
                for (int mt = 0; mt < 2; mt++)
#pragma unroll
                    for (int kk = 0; kk < 4; kk++) {
                        int c0 = nb + 16 * kk + coff;
                        int c1 = c0 + 8;
                        float b00 = b1v[c0], b01 = b1v[c0 + 1];
                        float b10 = b1v[c1], b11 = b1v[c1 + 1];
                        const float* d0 = acc[mt][2 * kk];
                        const float* d1 = acc[mt][2 * kk + 1];
                        float2 v;
                        v.x = fmaxf(d0[0] + b00, 0.f); v.y = fmaxf(d0[1] + b01, 0.f);
                        ah[mt][kk][0] = h2u(__float22half2_rn(v));
                        v.x = fmaxf(d0[2] + b00, 0.f); v.y = fmaxf(d0[3] + b01, 0.f);
                        ah[mt][kk][1] = h2u(__float22half2_rn(v));
                        v.x = fmaxf(d1[0] + b10, 0.f); v.y = fmaxf(d1[1] + b11, 0.f);
                        ah[mt][kk][2] = h2u(__float22half2_rn(v));
                        v.x = fmaxf(d1[2] + b10, 0.f); v.y = fmaxf(d1[3] + b11, 0.f);
                        ah[mt][kk][3] = h2u(__float22half2_rn(v));
                    }

                // ---- layer 2: own k-groups from regs ----
#pragma unroll
                for (int mt = 0; mt < 2; mt++)
#pragma unroll
                    for (int nt = 0; nt < 8; nt++)
#pragma unroll
                        for (int i = 0; i < 4; i++) acc[mt][nt][i] = 0.0f;
#pragma unroll
                for (int kk = 0; kk < 4; kk++) {
                    int kgg = 4 * hh + kk;
#pragma unroll
                    for (int jn = 0; jn < 4; jn++) {
                        uint32_t bf[4];
                        ldsm4(bf, Wb + swz(nb + jn * 16 + brow, 2 * (16 * kgg + bcol)));
                        mma16816(acc[0][2 * jn],     ah[0][kk], bf);
                        mma16816(acc[0][2 * jn + 1], ah[0][kk], bf + 2);
                        mma16816(acc[1][2 * jn],     ah[1][kk], bf);
                        mma16816(acc[1][2 * jn + 1], ah[1][kk], bf + 2);
                    }
                }
                // ---- layer 2: partner k-groups via 2-round SMEM exchange ----
#pragma unroll
                for (int r = 0; r < 2; r++) {
#pragma unroll
                    for (int t = 0; t < 2; t++) {
                        int kk = 2 * r + t;
                        int rc = 32 * hh + 16 * t;
#pragma unroll
                        for (int mt = 0; mt < 2; mt++) {
                            int row = m0 + 16 * mt + q;
                            *(uint32_t*)(Hc + swzH(row,     2 * (rc + coff)))     = ah[mt][kk][0];
                            *(uint32_t*)(Hc + swzH(row + 8, 2 * (rc + coff)))     = ah[mt][kk][1];
                            *(uint32_t*)(Hc + swzH(row,     2 * (rc + 8 + coff))) = ah[mt][kk][2];
                            *(uint32_t*)(Hc + swzH(row + 8, 2 * (rc + 8 + coff))) = ah[mt][kk][3];
                        }
                    }
                    PAIR_BAR(pbar);
#pragma unroll
                    for (int t = 0; t < 2; t++) {
                        int kgg = 4 * (1 - hh) + 2 * r + t;
                        int rc  = 32 * (1 - hh) + 16 * t;
                        uint32_t a0[4], a1[4];
                        ldsm4(a0, Hr + swzH(m0 + arow,      2 * (rc + acolh)));
                        ldsm4(a1, Hr + swzH(m0 + 16 + arow, 2 * (rc + acolh)));
#pragma unroll
                        for (int jn = 0; jn < 4; jn++) {
                            uint32_t bf[4];
                            ldsm4(bf, Wb + swz(nb + jn * 16 + brow, 2 * (16 * kgg + bcol)));
                            mma16816(acc[0][2 * jn],     a0, bf);
                            mma16816(acc[0][2 * jn + 1], a0, bf + 2);
                            mma16816(acc[1][2 * jn],     a1, bf);
                            mma16816(acc[1][2 * jn + 1], a1, bf + 2);
                        }
                    }
                    PAIR_BAR(pbar);
                }

                // ---- head: per-row dot over own 64 cols, pair-combine ----
                if (pass == 0) {
                    float pr[2][2] = {{0.f, 0.f}, {0.f, 0.f}};
#pragma unroll
                    for (int mt = 0; mt < 2; mt++)
#pragma unroll
                        for (int nt = 0; nt < 8; nt++) {
                            int c = nb + nt * 8 + coff;
                            float b0 = sb[128 + c], b1 = sb[128 + c + 1];
                            float w0 = sb[256 + c], w1 = sb[256 + c + 1];
                            pr[mt][0] = fmaf(fmaxf(acc[mt][nt][0] + b0, 0.f), w0, pr[mt][0]);
                            pr[mt][0] = fmaf(fmaxf(acc[mt][nt][1] + b1, 0.f), w1, pr[mt][0]);
                            pr[mt][1] = fmaf(fmaxf(acc[mt][nt][2] + b0, 0.f), w0, pr[mt][1]);
                            pr[mt][1] = fmaf(fmaxf(acc[mt][nt][3] + b1, 0.f), w1, pr[mt][1]);
                        }
#pragma unroll
                    for (int mt = 0; mt < 2; mt++)
#pragma unroll
                        for (int h = 0; h < 2; h++) {
                            float v = pr[mt][h];
                            v += __shfl_xor_sync(0xFFFFFFFFu, v, 1);
                            v += __shfl_xor_sync(0xFFFFFFFFu, v, 2);
                            if ((lane & 3) == 0) {
                                int rl = 16 * mt + q + 8 * h;
                                *(float*)(Hc + (m0 + rl) * 128 + hh * 64) = v;
                            }
                        }
                    PAIR_BAR(pbar);
                    if (hh == 0 && (lane & 3) == 0) {
#pragma unroll
                        for (int mt = 0; mt < 2; mt++)
#pragma unroll
                            for (int h = 0; h < 2; h++) {
                                int rl = 16 * mt + q + 8 * h;
                                float v = *(float*)(Hc + (m0 + rl) * 128)
                                        + *(float*)(Hc + (m0 + rl) * 128 + 64) + sb[1024];
                                out[tile * 128 + m0 + rl] = v;
                            }
                    }
                    PAIR_BAR(pbar);
                } else {
                    float pr[2][2][3];
#pragma unroll
                    for (int mt = 0; mt < 2; mt++)
#pragma unroll
                        for (int h = 0; h < 2; h++)
#pragma unroll
                            for (int ch = 0; ch < 3; ch++) pr[mt][h][ch] = 0.f;
#pragma unroll
                    for (int mt = 0; mt < 2; mt++)
#pragma unroll
                        for (int nt = 0; nt < 8; nt++) {
                            int c = nb + nt * 8 + coff;
                            float b0 = sb[512 + c], b1 = sb[512 + c + 1];
                            float g0 = fmaxf(acc[mt][nt][0] + b0, 0.f);
                            float g1 = fmaxf(acc[mt][nt][1] + b1, 0.f);
                            float g2 = fmaxf(acc[mt][nt][2] + b0, 0.f);
                            float g3 = fmaxf(acc[mt][nt][3] + b1, 0.f);
#pragma unroll
                            for (int ch = 0; ch < 3; ch++) {
                                float wc0 = sb[640 + 3 * c + ch];
                                float wc1 = sb[640 + 3 * (c + 1) + ch];
                                pr[mt][0][ch] = fmaf(g0, wc0, pr[mt][0][ch]);
                                pr[mt][0][ch] = fmaf(g1, wc1, pr[mt][0][ch]);
                                pr[mt][1][ch] = fmaf(g2, wc0, pr[mt][1][ch]);
                                pr[mt][1][ch] = fmaf(g3, wc1, pr[mt][1][ch]);
                            }
                        }
#pragma unroll
                    for (int mt = 0; mt < 2; mt++)
#pragma unroll
                        for (int h = 0; h < 2; h++) {
                            float v0 = pr[mt][h][0], v1 = pr[mt][h][1], v2 = pr[mt][h][2];
                            v0 += __shfl_xor_sync(0xFFFFFFFFu, v0, 1);
                            v0 += __shfl_xor_sync(0xFFFFFFFFu, v0, 2);
                            v1 += __shfl_xor_sync(0xFFFFFFFFu, v1, 1);
                            v1 += __shfl_xor_sync(0xFFFFFFFFu, v1, 2);
                            v2 += __shfl_xor_sync(0xFFFFFFFFu, v2, 1);
                            v2 += __shfl_xor_sync(0xFFFFFFFFu, v2, 2);
                            if ((lane & 3) == 0) {
                                int rl = 16 * mt + q + 8 * h;
                                float* hs = (float*)(Hc + (m0 + rl) * 128 + hh * 64);
                                hs[0] = v0; hs[1] = v1; hs[2] = v2;
                            }
                        }
                    PAIR_BAR(pbar);
                    if (hh == 0 && (lane & 3) == 0) {
#pragma unroll
                        for (int mt = 0; mt < 2; mt++)
#pragma unroll
                            for (int h = 0; h < 2; h++) {
                                int rl = 16 * mt + q + 8 * h;
                                const float* h0 = (const float*)(Hc + (m0 + rl) * 128);
                                const float* h1 = (const float*)(Hc + (m0 + rl) * 128 + 64);
                                float* ro = out + TOT + 3 * (tile * 128 + m0 + rl);
                                ro[0] = 1.0f / (1.0f + __expf(-(h0[0] + h1[0] + sb[1025])));
                                ro[1] = 1.0f / (1.0f + __expf(-(h0[1] + h1[1] + sb[1026])));
                                ro[2] = 1.0f / (1.0f + __expf(-(h0[2] + h1[2] + sb[1027])));
                            }
                    }
                    PAIR_BAR(pbar);
                }
            }
        }
    }
}

// ---------------------------------------------------------------------------
// kernel_launch
// ---------------------------------------------------------------------------
extern "C" void kernel_launch(void* const* d_in, const int* in_sizes, int n_in,
                              void* d_out, int out_size) {
    const float* triplane = (const float*)d_in[0];
    const float* coords   = (const float*)d_in[1];
    const float* vdirs    = (const float*)d_in[2];
    const float* dw1 = (const float*)d_in[3];
    const float* db1 = (const float*)d_in[4];
    const float* dw2 = (const float*)d_in[5];
    const float* db2 = (const float*)d_in[6];
    const float* dw3 = (const float*)d_in[7];
    const float* db3 = (const float*)d_in[8];
    const float* cw1 = (const float*)d_in[9];
    const float* cb1 = (const float*)d_in[10];
    const float* cw2 = (const float*)d_in[11];
    const float* cb2 = (const float*)d_in[12];
    const float* cw3 = (const float*)d_in[13];
    const float* cb3 = (const float*)d_in[14];
    float* out = (float*)d_out;

    k_dummy<<<1, 32>>>();   // shifts ncu -s 5 capture onto k_main
    k_transpose<<<(NPLANES * HWIM + 255) / 256, 256>>>(triplane);
    k_prep_w<<<(4 * 128 * 128 + 255) / 256, 256>>>(dw1, dw2, cw1, cw2);

    int dev = 0, sms = 148;
    cudaGetDevice(&dev);
    cudaDeviceGetAttribute(&sms, cudaDevAttrMultiProcessorCount, dev);
    cudaFuncSetAttribute(k_main, cudaFuncAttributeMaxDynamicSharedMemorySize, SMEM_BYTES);
    k_main<<<sms, NTHREADS, SMEM_BYTES>>>(coords, vdirs, db1, db2, dw3, db3,
                                          cb1, cb2, cw3, cb3, out);
}